// round 15
// baseline (speedup 1.0000x reference)
#include <cuda_runtime.h>
#include <cuda_fp16.h>

#define SEQ     2048
#define DM      2048
#define NHEAD   16
#define LAMBDA_INIT 0.8f
#define NELEM   (SEQ * DM)

typedef unsigned int u32;

// ---------------- device scratch (no allocations) ----------------
__device__ __half s_Xf[NELEM];                  // x fp16
__device__ __half s_WT[4][NELEM];               // WqT,WkT,WvT,WoT fp16
__device__ __half s_Qf[NELEM];                  // Q fp16, pre-scaled 1/8
__device__ __half s_Kf[NELEM];
__device__ __half s_Vf[NELEM];
__device__ __half s_AO[NELEM];                  // attn out fp16

// ---------------- PTX helpers (sm_80+ portable) ----------------
__device__ __forceinline__ u32 smem_u32(const void* p) {
    u32 a;
    asm("{ .reg .u64 t; cvta.to.shared.u64 t, %1; cvt.u32.u64 %0, t; }" : "=r"(a) : "l"(p));
    return a;
}

#define CP16(saddr, gptr) \
    asm volatile("cp.async.cg.shared.global [%0], [%1], 16;" :: "r"((u32)(saddr)), "l"(gptr))
#define CP_COMMIT() asm volatile("cp.async.commit_group;" ::: "memory")
#define CP_WAIT0()  asm volatile("cp.async.wait_group 0;" ::: "memory")
#define CP_WAIT1()  asm volatile("cp.async.wait_group 1;" ::: "memory")

#define LDSM4(d, addr) \
    asm volatile("ldmatrix.sync.aligned.m8n8.x4.shared.b16 {%0,%1,%2,%3}, [%4];" \
        : "=r"((d)[0]), "=r"((d)[1]), "=r"((d)[2]), "=r"((d)[3]) : "r"((u32)(addr)))
#define LDSM4T(d, addr) \
    asm volatile("ldmatrix.sync.aligned.m8n8.x4.trans.shared.b16 {%0,%1,%2,%3}, [%4];" \
        : "=r"((d)[0]), "=r"((d)[1]), "=r"((d)[2]), "=r"((d)[3]) : "r"((u32)(addr)))
#define LDSM2(d0, d1, addr) \
    asm volatile("ldmatrix.sync.aligned.m8n8.x2.shared.b16 {%0,%1}, [%2];" \
        : "=r"(d0), "=r"(d1) : "r"((u32)(addr)))

#define MMAH(acc, a, b0, b1) \
    asm volatile("mma.sync.aligned.m16n8k16.row.col.f32.f16.f16.f32 " \
        "{%0,%1,%2,%3}, {%4,%5,%6,%7}, {%8,%9}, {%0,%1,%2,%3};" \
        : "+f"((acc)[0]), "+f"((acc)[1]), "+f"((acc)[2]), "+f"((acc)[3]) \
        : "r"((a)[0]), "r"((a)[1]), "r"((a)[2]), "r"((a)[3]), "r"(b0), "r"(b1))

__device__ __forceinline__ u32 packh2(float a, float b) {
    __half2 t = __floats2half2_rn(a, b);
    return *(u32*)&t;
}

// ---------------------------------------------------------------------------
// Dense fp16 HMMA GEMM body (m64n32 warp tiles, 256 threads).
// K-chunk 64: 3 smem buffers, cp.async prefetch distance 1, ONE
// __syncthreads per chunk (32 barriers total for K=2048).
// C[m][n] = cs * sum_k A[m][k]*B[n][k].  Tile 128x128.
// ---------------------------------------------------------------------------
#define TSTRIDE 144                  // 64 halfs (128 B) + 16 B pad
#define TILEB   (128 * TSTRIDE)      // 18432
#define STAGEB  (2 * TILEB)          // A + B tile = 36864 B
#define OFF_B   TILEB
#define NSTAGE  3

template<typename CT>
__device__ __forceinline__ void gemm_body(
    const __half* __restrict__ A, int lda,
    const __half* __restrict__ B, int ldb,
    CT* __restrict__ C, int ldc, int K, float cs)
{
    extern __shared__ char smem[];
    const u32 sb = smem_u32(smem);

    const int tid = threadIdx.x;
    const int wid = tid >> 5;
    const int lid = tid & 31;
    const int row0 = blockIdx.y * 128;
    const int col0 = blockIdx.x * 128;
    const int wm0 = (wid & 1) * 64;
    const int wn0 = (wid >> 1) * 32;

    // loader: 64 B of one A row + 64 B of one B row per thread per chunk
    const int lr = tid >> 1;
    const int lq = tid & 1;
    const __half* gA = A + (long long)(row0 + lr) * lda + lq * 32;
    const __half* gB = B + (long long)(col0 + lr) * ldb + lq * 32;
    const u32 sRow = sb + (u32)(lr * TSTRIDE + lq * 64);

    const int r8  = lid & 7;
    const int seg = lid >> 3;
    const u32 aLane = (u32)(((seg & 1) * 8 + r8) * TSTRIDE + (seg >> 1) * 16);
    const u32 bLane = (u32)(r8 * TSTRIDE + (seg & 1) * 16);

    float acc[4][4][4];
#pragma unroll
    for (int mi = 0; mi < 4; mi++)
#pragma unroll
        for (int ni = 0; ni < 4; ni++)
#pragma unroll
            for (int q = 0; q < 4; q++) acc[mi][ni][q] = 0.0f;

    const int nch = K >> 6;

#define LOADC(ck, st) do {                                                    \
        const u32 s0 = sRow + (u32)(st) * STAGEB;                             \
        const long long kg = (long long)(ck) * 64;                            \
        CP16(s0,      gA + kg);       CP16(s0 + 16, gA + kg + 8);             \
        CP16(s0 + 32, gA + kg + 16);  CP16(s0 + 48, gA + kg + 24);            \
        CP16(s0 + OFF_B,      gB + kg);       CP16(s0 + OFF_B + 16, gB + kg + 8); \
        CP16(s0 + OFF_B + 32, gB + kg + 16);  CP16(s0 + OFF_B + 48, gB + kg + 24); \
        CP_COMMIT();                                                          \
    } while (0)

    // prologue: 1 chunk in flight (prefetch distance 1, 3 buffers)
    LOADC(0, 0);

    int stage = 0;
    for (int ck = 0; ck < nch; ck++) {
        if (ck + 1 < nch) {
            // writes stage (ck+1)%3 == (ck-2)%3: last read at iter ck-2,
            // protected by the barriers at iterations ck-1 and ck.
            int nst = stage + 1; if (nst == NSTAGE) nst = 0;
            LOADC(ck + 1, nst);
            CP_WAIT1();
        } else {
            CP_WAIT0();
        }
        __syncthreads();    // single barrier per chunk: visibility + stage guard

        const u32 stg   = sb + (u32)stage * STAGEB;
        const u32 aBase = stg + (u32)(wm0 * TSTRIDE) + aLane;
        const u32 bBase = stg + (u32)(OFF_B + wn0 * TSTRIDE) + bLane;
        stage++; if (stage == NSTAGE) stage = 0;

#pragma unroll
        for (int ks = 0; ks < 4; ks++) {
            const u32 kb = (u32)(ks * 32);
            u32 b0[4], b1[4];
#pragma unroll
            for (int ni = 0; ni < 4; ni++)
                LDSM2(b0[ni], b1[ni], bBase + kb + (u32)(ni * 8 * TSTRIDE));
            u32 a[4][4];
#pragma unroll
            for (int mi = 0; mi < 4; mi++)
                LDSM4(a[mi], aBase + kb + (u32)(mi * 16 * TSTRIDE));
#pragma unroll
            for (int ni = 0; ni < 4; ni++)
#pragma unroll
                for (int mi = 0; mi < 4; mi++)
                    MMAH(acc[mi][ni], a[mi], b0[ni], b1[ni]);
        }
    }
#undef LOADC

    const int rb = row0 + wm0 + (lid >> 2);
    const int cb = col0 + wn0 + (lid & 3) * 2;
#pragma unroll
    for (int mi = 0; mi < 4; mi++) {
#pragma unroll
        for (int ni = 0; ni < 4; ni++) {
            CT* p0 = C + (long long)(rb + mi * 16) * ldc + cb + ni * 8;
            CT* p1 = p0 + 8ll * ldc;
            if (sizeof(CT) == 2) {
                *(__half2*)p0 = __floats2half2_rn(acc[mi][ni][0] * cs, acc[mi][ni][1] * cs);
                *(__half2*)p1 = __floats2half2_rn(acc[mi][ni][2] * cs, acc[mi][ni][3] * cs);
            } else {
                *(float2*)p0 = make_float2(acc[mi][ni][0] * cs, acc[mi][ni][1] * cs);
                *(float2*)p1 = make_float2(acc[mi][ni][2] * cs, acc[mi][ni][3] * cs);
            }
        }
    }
}

// Batched QKV projection: z selects weight + destination (Q scaled by 1/8)
__global__ __launch_bounds__(256, 2)
void qkv_gemm()
{
    const int z = blockIdx.z;
    __half* C = (z == 0) ? s_Qf : ((z == 1) ? s_Kf : s_Vf);
    gemm_body<__half>(s_Xf, DM, s_WT[z], DM, C, DM, DM, (z == 0) ? 0.125f : 1.0f);
}

// Output projection
__global__ __launch_bounds__(256, 2)
void wo_gemm(float* __restrict__ out)
{
    gemm_body<float>(s_AO, DM, s_WT[3], DM, out, DM, DM, 1.0f);
}

// ---------------------------------------------------------------------------
// Fused differential attention, 512 threads (R13 config — best known):
//  warps 0-7 = variant 1, warps 8-15 = variant 2 (each m16 of 128 q rows).
//  64-key K/V tiles, 3-stage prefetch-1 pipeline, ONE __syncthreads per tile.
//  Q fragments hoisted; QK -> exp -> PV interleaved per 16-key slab.
//  exp without max-sub (scores bounded). Combine through smem, GroupNorm
//  + *(0.2) -> fp16 s_AO.  lambda in-block.
// ---------------------------------------------------------------------------
#define BQ     128
#define KT     64
#define QSTR   272                  // 128 halfs + 16B pad
#define SQB2   (BQ * QSTR)          // 34816
#define KTB    (KT * QSTR)          // 17408
#define STG2B  (2 * KTB)            // K + V per stage = 34816
#define NKVST  3
#define FSTR   132                  // combine buffer stride (floats)

__global__ __launch_bounds__(512, 1)
void attn_fused(const float* __restrict__ gnw, const float* __restrict__ gnb,
                const float* __restrict__ lq1, const float* __restrict__ lk1,
                const float* __restrict__ lq2, const float* __restrict__ lk2)
{
    extern __shared__ char sm[];
    const u32 sb  = smem_u32(sm);
    const u32 sQ  = sb;
    const u32 sKV = sb + SQB2;
    float* fbuf = (float*)(sm + SQB2);                 // reuses KV region
    float* shw  = (float*)(sm + SQB2 + NKVST * STG2B);

    const int tid = threadIdx.x;
    const int wid = tid >> 5;
    const int lid = tid & 31;
    const int q0  = blockIdx.x * BQ;
    const int h   = blockIdx.y;
    const int v   = wid >> 3;                          // variant
    const int wm  = (wid & 7) * 16;                    // warp's m-rows

    if (tid < 128) {
        shw[tid]       = gnw[h * 128 + tid];
        shw[128 + tid] = gnb[h * 128 + tid];
    }
    if (wid == 15) {
        float a = lq1[lid] * lk1[lid] + lq1[lid + 32] * lk1[lid + 32];
        float b = lq2[lid] * lk2[lid] + lq2[lid + 32] * lk2[lid + 32];
#pragma unroll
        for (int o = 16; o; o >>= 1) {
            a += __shfl_xor_sync(0xffffffffu, a, o);
            b += __shfl_xor_sync(0xffffffffu, b, o);
        }
        if (lid == 0) shw[256] = __expf(a) - __expf(b) + LAMBDA_INIT;
    }

    // --- Q loader: 512 threads, 4 CP16 each ---
    {
        const int qr = tid >> 2, qs = tid & 3;
        const __half* gq = s_Qf + (long long)(q0 + qr) * DM + h * 128 + qs * 32;
        const u32 d = sQ + (u32)(qr * QSTR + qs * 64);
#pragma unroll
        for (int j = 0; j < 4; j++) CP16(d + j * 16, gq + j * 8);
        CP_COMMIT();
    }
    // --- KV loader mapping: 8 threads/row, 2 CP16 per K and V row ---
    const int kr = tid >> 3, ks = tid & 7;
    const __half* gK0 = s_Kf + (long long)kr * DM + h * 128 + ks * 16;
    const __half* gV0 = s_Vf + (long long)kr * DM + h * 128 + ks * 16;
    const u32 kvDst = (u32)(kr * QSTR + ks * 32);

#define LOADKV(t, st) do {                                                    \
        const u32 d = sKV + (u32)(st) * STG2B + kvDst;                        \
        const __half* gk = gK0 + (long long)(t) * KT * DM;                    \
        const __half* gv = gV0 + (long long)(t) * KT * DM;                    \
        CP16(d, gk);        CP16(d + 16, gk + 8);                             \
        CP16(d + KTB, gv);  CP16(d + KTB + 16, gv + 8);                       \
        CP_COMMIT();                                                          \
    } while (0)

    LOADKV(0, 0);

    // --- fragment lane offsets ---
    const int r8  = lid & 7;
    const int seg = lid >> 3;
    const u32 aOff  = sQ + (u32)((wm + (seg & 1) * 8 + r8) * QSTR + (seg >> 1) * 16 + v * 128);
    const u32 bLane = (u32)(((lid >> 4) * 8 + r8) * QSTR + ((lid >> 3) & 1) * 16 + v * 128);
    const u32 vLane = (u32)((((lid >> 3) & 1) * 8 + r8) * QSTR + (lid >> 4) * 16);

    // --- hoist Q fragments (loop-invariant): wait for Q cp.async group ---
    CP_WAIT1();             // oldest group (Q) retired; KV(0) may be pending
    __syncthreads();
    u32 qf[4][4];
#pragma unroll
    for (int kt = 0; kt < 4; kt++)
        LDSM4(qf[kt], aOff + (u32)(kt * 32));

    float O[16][4];
#pragma unroll
    for (int ni = 0; ni < 16; ni++)
#pragma unroll
        for (int q = 0; q < 4; q++) O[ni][q] = 0.0f;
    float la = 0.0f, lb = 0.0f;

    int stage = 0;
#pragma unroll 1
    for (int t = 0; t < 32; t++) {
        if (t + 1 < 32) {
            // writes stage (t+1)%3 == (t-2)%3: last read at iter t-2,
            // protected by barriers at iterations t-1 and t.
            int nst = stage + 1; if (nst == NKVST) nst = 0;
            LOADKV(t + 1, nst);
            CP_WAIT1();
        } else {
            CP_WAIT0();
        }
        __syncthreads();    // single barrier per tile

        const u32 sK = sKV + (u32)stage * STG2B;
        const u32 sV = sK + KTB;
        stage++; if (stage == NKVST) stage = 0;

        // --- interleaved: per 16-key slab np: QK -> exp -> PV(kt=np) ---
#pragma unroll
        for (int np = 0; np < 4; np++) {
            // S slab = Q * K^T (m16 x n16 x k64)
            float accS[2][4];
#pragma unroll
            for (int q = 0; q < 4; q++) { accS[0][q] = 0.0f; accS[1][q] = 0.0f; }
#pragma unroll
            for (int kt = 0; kt < 4; kt++) {
                u32 b[4];
                LDSM4(b, sK + bLane + (u32)(np * 16 * QSTR + kt * 32));
                MMAH(accS[0], qf[kt], b[0], b[1]);
                MMAH(accS[1], qf[kt], b[2], b[3]);
            }

            // p = exp(s); row-sum; pack as A-fragment for PV step kt=np
            float e0 = __expf(accS[0][0]);
            float e1 = __expf(accS[0][1]);
            float e2 = __expf(accS[0][2]);
            float e3 = __expf(accS[0][3]);
            float f0 = __expf(accS[1][0]);
            float f1 = __expf(accS[1][1]);
            float f2 = __expf(accS[1][2]);
            float f3 = __expf(accS[1][3]);
            la += e0 + e1 + f0 + f1;
            lb += e2 + e3 + f2 + f3;
            u32 a2[4];
            a2[0] = packh2(e0, e1);
            a2[1] = packh2(e2, e3);
            a2[2] = packh2(f0, f1);
            a2[3] = packh2(f2, f3);

            // O += p_slab * V_slab (m16 x n128 x k16)
#pragma unroll
            for (int cp = 0; cp < 8; cp++) {
                u32 d[4];
                LDSM4T(d, sV + vLane + (u32)(np * 16 * QSTR + cp * 32));
                MMAH(O[2 * cp],     a2, d[0], d[1]);
                MMAH(O[2 * cp + 1], a2, d[2], d[3]);
            }
        }
    }
#undef LOADKV

    // --- finish row sums across the quad ---
#pragma unroll
    for (int o = 1; o <= 2; o <<= 1) {
        la += __shfl_xor_sync(0xffffffffu, la, o);
        lb += __shfl_xor_sync(0xffffffffu, lb, o);
    }

    __syncthreads();    // all warps done with KV smem -> fbuf reuse safe

    const int rr = wm + (lid >> 2);
    const int cq = (lid & 3) * 2;

    if (v == 1) {
        const float lam = shw[256];
        const float ia = lam / la, ib = lam / lb;
#pragma unroll
        for (int ni = 0; ni < 16; ni++) {
            *(float2*)&fbuf[rr * FSTR + ni * 8 + cq] =
                make_float2(O[ni][0] * ia, O[ni][1] * ia);
            *(float2*)&fbuf[(rr + 8) * FSTR + ni * 8 + cq] =
                make_float2(O[ni][2] * ib, O[ni][3] * ib);
        }
    } else {
        const float ia = 1.0f / la, ib = 1.0f / lb;
#pragma unroll
        for (int ni = 0; ni < 16; ni++) {
            O[ni][0] *= ia; O[ni][1] *= ia;
            O[ni][2] *= ib; O[ni][3] *= ib;
        }
    }
    __syncthreads();

    if (v == 0) {
        // combine + GroupNorm stats
        float su0 = 0.0f, su1 = 0.0f, sq0 = 0.0f, sq1 = 0.0f;
#pragma unroll
        for (int ni = 0; ni < 16; ni++) {
            float2 f0 = *(const float2*)&fbuf[rr * FSTR + ni * 8 + cq];
            float2 f1 = *(const float2*)&fbuf[(rr + 8) * FSTR + ni * 8 + cq];
            float v0 = O[ni][0] - f0.x;
            float v1 = O[ni][1] - f0.y;
            float v2 = O[ni][2] - f1.x;
            float v3 = O[ni][3] - f1.y;
            O[ni][0] = v0; O[ni][1] = v1; O[ni][2] = v2; O[ni][3] = v3;
            su0 += v0 + v1;  sq0 += v0 * v0 + v1 * v1;
            su1 += v2 + v3;  sq1 += v2 * v2 + v3 * v3;
        }
#pragma unroll
        for (int o = 1; o <= 2; o <<= 1) {
            su0 += __shfl_xor_sync(0xffffffffu, su0, o);
            su1 += __shfl_xor_sync(0xffffffffu, su1, o);
            sq0 += __shfl_xor_sync(0xffffffffu, sq0, o);
            sq1 += __shfl_xor_sync(0xffffffffu, sq1, o);
        }
        const float mn0 = su0 * (1.0f / 128.0f);
        const float mn1 = su1 * (1.0f / 128.0f);
        const float iv0 = rsqrtf(sq0 * (1.0f / 128.0f) - mn0 * mn0 + 1e-5f);
        const float iv1 = rsqrtf(sq1 * (1.0f / 128.0f) - mn1 * mn1 + 1e-5f);

        const int row0 = q0 + rr;
        const float post = 1.0f - LAMBDA_INIT;
#pragma unroll
        for (int ni = 0; ni < 16; ni++) {
            const int c = ni * 8 + cq;
            const float w0 = shw[c],       w1 = shw[c + 1];
            const float b0 = shw[128 + c], b1 = shw[128 + c + 1];
            float v0 = ((O[ni][0] - mn0) * iv0 * w0 + b0) * post;
            float v1 = ((O[ni][1] - mn0) * iv0 * w1 + b1) * post;
            float v2 = ((O[ni][2] - mn1) * iv1 * w0 + b0) * post;
            float v3 = ((O[ni][3] - mn1) * iv1 * w1 + b1) * post;

            const long long off = (long long)row0 * DM + h * 128 + c;
            __half2 hh;
            hh = __floats2half2_rn(v0, v1); *(u32*)(s_AO + off)            = *(u32*)&hh;
            hh = __floats2half2_rn(v2, v3); *(u32*)(s_AO + off + 8ll * DM) = *(u32*)&hh;
        }
    }
}

// ---------------------------------------------------------------------------
// fp32 -> fp16 conversion of x
// ---------------------------------------------------------------------------
__global__ __launch_bounds__(256)
void conv_kernel(const float* __restrict__ src)
{
    const int i = (blockIdx.x * blockDim.x + threadIdx.x) * 8;
    float4 a = *(const float4*)(src + i);
    float4 b = *(const float4*)(src + i + 4);
    __half2 h[4];
    h[0] = __floats2half2_rn(a.x, a.y);
    h[1] = __floats2half2_rn(a.z, a.w);
    h[2] = __floats2half2_rn(b.x, b.y);
    h[3] = __floats2half2_rn(b.z, b.w);
    *(uint4*)(s_Xf + i) = *(uint4*)h;
}

// fp32 [2048][2048] -> transposed fp16, batched over the 4 weight matrices
__global__ __launch_bounds__(256)
void convT4_kernel(const float* __restrict__ w0, const float* __restrict__ w1,
                   const float* __restrict__ w2, const float* __restrict__ w3)
{
    const float* src = (blockIdx.z == 0) ? w0 : (blockIdx.z == 1) ? w1
                     : (blockIdx.z == 2) ? w2 : w3;
    __half* dst = s_WT[blockIdx.z];

    __shared__ float tile[32][33];
    const int bx = blockIdx.x * 32;
    const int by = blockIdx.y * 32;
    const int tx = threadIdx.x, ty = threadIdx.y;
#pragma unroll
    for (int i = 0; i < 32; i += 8)
        tile[ty + i][tx] = src[(long long)(by + ty + i) * DM + bx + tx];
    __syncthreads();
#pragma unroll
    for (int i = 0; i < 32; i += 8)
        dst[(long long)(bx + ty + i) * DM + by + tx] = __float2half_rn(tile[tx][ty + i]);
}

// ---------------------------------------------------------------------------
// Host launch
// ---------------------------------------------------------------------------
extern "C" void kernel_launch(void* const* d_in, const int* in_sizes, int n_in,
                              void* d_out, int out_size)
{
    (void)in_sizes; (void)n_in; (void)out_size;

    const float* x   = (const float*)d_in[0];
    const float* Wq  = (const float*)d_in[1];
    const float* Wk  = (const float*)d_in[2];
    const float* Wv  = (const float*)d_in[3];
    const float* Wo  = (const float*)d_in[4];
    const float* lq1 = (const float*)d_in[5];
    const float* lk1 = (const float*)d_in[6];
    const float* lq2 = (const float*)d_in[7];
    const float* lk2 = (const float*)d_in[8];
    const float* gnw = (const float*)d_in[9];
    const float* gnb = (const float*)d_in[10];
    float* out = (float*)d_out;

    const int SMG = NSTAGE * STAGEB;                     // 110592
    const int SMA = SQB2 + NKVST * STG2B + 1088;         // ~140.4 KB
    cudaFuncSetAttribute(qkv_gemm,   cudaFuncAttributeMaxDynamicSharedMemorySize, SMG);
    cudaFuncSetAttribute(wo_gemm,    cudaFuncAttributeMaxDynamicSharedMemorySize, SMG);
    cudaFuncSetAttribute(attn_fused, cudaFuncAttributeMaxDynamicSharedMemorySize, SMA);

    // input conversions
    conv_kernel<<<NELEM / 2048, 256>>>(x);
    convT4_kernel<<<dim3(64, 64, 4), dim3(32, 8)>>>(Wq, Wk, Wv, Wo);

    // QKV projections (one batched launch, z = 0..2)
    qkv_gemm<<<dim3(16, 16, 3), 256, SMG>>>();

    // fused attention + combine + GroupNorm (lambda in-block)
    attn_fused<<<dim3(16, 16), 512, SMA>>>(gnw, gnb, lq1, lk1, lq2, lk2);

    // output projection
    wo_gemm<<<dim3(16, 16), 256, SMG>>>(out);
}

// round 16
// speedup vs baseline: 1.0591x; 1.0591x over previous
#include <cuda_runtime.h>
#include <cuda_fp16.h>

#define SEQ     2048
#define DM      2048
#define NHEAD   16
#define LAMBDA_INIT 0.8f
#define NELEM   (SEQ * DM)

typedef unsigned int u32;

// ---------------- device scratch (no allocations) ----------------
__device__ __half s_Xf[NELEM];                  // x fp16
__device__ __half s_WT[4][NELEM];               // WqT,WkT,WvT,WoT fp16
__device__ __half s_Qf[NELEM];                  // Q fp16, pre-scaled 1/8
__device__ __half s_Kf[NELEM];
__device__ __half s_Vf[NELEM];
__device__ __half s_AO[NELEM];                  // attn out fp16

// ---------------- PTX helpers (sm_80+ portable) ----------------
__device__ __forceinline__ u32 smem_u32(const void* p) {
    u32 a;
    asm("{ .reg .u64 t; cvta.to.shared.u64 t, %1; cvt.u32.u64 %0, t; }" : "=r"(a) : "l"(p));
    return a;
}

#define CP16(saddr, gptr) \
    asm volatile("cp.async.cg.shared.global [%0], [%1], 16;" :: "r"((u32)(saddr)), "l"(gptr))
#define CP_COMMIT() asm volatile("cp.async.commit_group;" ::: "memory")
#define CP_WAIT0()  asm volatile("cp.async.wait_group 0;" ::: "memory")
#define CP_WAIT1()  asm volatile("cp.async.wait_group 1;" ::: "memory")
#define CP_WAIT2()  asm volatile("cp.async.wait_group 2;" ::: "memory")

#define LDSM4(d, addr) \
    asm volatile("ldmatrix.sync.aligned.m8n8.x4.shared.b16 {%0,%1,%2,%3}, [%4];" \
        : "=r"((d)[0]), "=r"((d)[1]), "=r"((d)[2]), "=r"((d)[3]) : "r"((u32)(addr)))
#define LDSM4T(d, addr) \
    asm volatile("ldmatrix.sync.aligned.m8n8.x4.trans.shared.b16 {%0,%1,%2,%3}, [%4];" \
        : "=r"((d)[0]), "=r"((d)[1]), "=r"((d)[2]), "=r"((d)[3]) : "r"((u32)(addr)))
#define LDSM2(d0, d1, addr) \
    asm volatile("ldmatrix.sync.aligned.m8n8.x2.shared.b16 {%0,%1}, [%2];" \
        : "=r"(d0), "=r"(d1) : "r"((u32)(addr)))

#define MMAH(acc, a, b0, b1) \
    asm volatile("mma.sync.aligned.m16n8k16.row.col.f32.f16.f16.f32 " \
        "{%0,%1,%2,%3}, {%4,%5,%6,%7}, {%8,%9}, {%0,%1,%2,%3};" \
        : "+f"((acc)[0]), "+f"((acc)[1]), "+f"((acc)[2]), "+f"((acc)[3]) \
        : "r"((a)[0]), "r"((a)[1]), "r"((a)[2]), "r"((a)[3]), "r"(b0), "r"(b1))

__device__ __forceinline__ u32 packh2(float a, float b) {
    __half2 t = __floats2half2_rn(a, b);
    return *(u32*)&t;
}

// ---------------------------------------------------------------------------
// Dense fp16 HMMA GEMM body (R11/R13 champion config: m64n32 warp tiles,
// 256 threads).  K-chunk 32, 4 smem buffers, cp.async prefetch distance 2,
// ONE __syncthreads per chunk.
// C[m][n] = cs * sum_k A[m][k]*B[n][k].  Tile 128x128.
// ---------------------------------------------------------------------------
#define TSTRIDE 80
#define TILEB   (128 * TSTRIDE)
#define STAGEB  (2 * TILEB)          // A tile + B tile = 20480 B
#define OFF_B   TILEB
#define NSTAGE  4

template<typename CT>
__device__ __forceinline__ void gemm_body(
    const __half* __restrict__ A, int lda,
    const __half* __restrict__ B, int ldb,
    CT* __restrict__ C, int ldc, int K, float cs)
{
    extern __shared__ char smem[];
    const u32 sb = smem_u32(smem);

    const int tid = threadIdx.x;
    const int wid = tid >> 5;
    const int lid = tid & 31;
    const int row0 = blockIdx.y * 128;
    const int col0 = blockIdx.x * 128;
    const int wm0 = (wid & 1) * 64;
    const int wn0 = (wid >> 1) * 32;

    const int lr = tid >> 1;
    const int lq = tid & 1;
    const __half* gA = A + (long long)(row0 + lr) * lda + lq * 16;
    const __half* gB = B + (long long)(col0 + lr) * ldb + lq * 16;
    const u32 sRow = sb + (u32)(lr * TSTRIDE + lq * 32);

    const int r8  = lid & 7;
    const int seg = lid >> 3;
    const u32 aLane = (u32)(((seg & 1) * 8 + r8) * TSTRIDE + (seg >> 1) * 16);
    const u32 bLane = (u32)(r8 * TSTRIDE + (seg & 1) * 16);

    float acc[4][4][4];
#pragma unroll
    for (int mi = 0; mi < 4; mi++)
#pragma unroll
        for (int ni = 0; ni < 4; ni++)
#pragma unroll
            for (int q = 0; q < 4; q++) acc[mi][ni][q] = 0.0f;

    const int nch = K >> 5;

#define LOADC(ck, st) do {                                                    \
        const u32 s0 = sRow + (u32)(st) * STAGEB;                             \
        const long long kg = (long long)(ck) * 32;                            \
        CP16(s0, gA + kg);          CP16(s0 + 16, gA + kg + 8);               \
        CP16(s0 + OFF_B, gB + kg);  CP16(s0 + OFF_B + 16, gB + kg + 8);       \
        CP_COMMIT();                                                          \
    } while (0)

    // prologue: 2 chunks in flight (prefetch distance 2, 4 buffers)
    LOADC(0, 0);
    LOADC(1, 1);

    for (int ck = 0; ck < nch; ck++) {
        if (ck + 2 < nch) {
            // writes stage (ck+2)&3 == (ck-2)&3: last read at iter ck-2,
            // protected by the barriers at iterations ck-1 and ck.
            LOADC(ck + 2, (ck + 2) & (NSTAGE - 1));
            CP_WAIT2();
        } else if (ck + 1 < nch) {
            CP_WAIT1();
        } else {
            CP_WAIT0();
        }
        __syncthreads();    // single barrier per chunk: visibility + stage guard

        const u32 stg   = sb + (u32)((ck & (NSTAGE - 1)) * STAGEB);
        const u32 aBase = stg + (u32)(wm0 * TSTRIDE) + aLane;
        const u32 bBase = stg + (u32)(OFF_B + wn0 * TSTRIDE) + bLane;

#pragma unroll
        for (int ks = 0; ks < 2; ks++) {
            const u32 kb = (u32)(ks * 32);
            u32 b0[4], b1[4];
#pragma unroll
            for (int ni = 0; ni < 4; ni++)
                LDSM2(b0[ni], b1[ni], bBase + kb + (u32)(ni * 8 * TSTRIDE));
            u32 a[4][4];
#pragma unroll
            for (int mi = 0; mi < 4; mi++)
                LDSM4(a[mi], aBase + kb + (u32)(mi * 16 * TSTRIDE));
#pragma unroll
            for (int ni = 0; ni < 4; ni++)
#pragma unroll
                for (int mi = 0; mi < 4; mi++)
                    MMAH(acc[mi][ni], a[mi], b0[ni], b1[ni]);
        }
    }
#undef LOADC

    const int rb = row0 + wm0 + (lid >> 2);
    const int cb = col0 + wn0 + (lid & 3) * 2;
#pragma unroll
    for (int mi = 0; mi < 4; mi++) {
#pragma unroll
        for (int ni = 0; ni < 4; ni++) {
            CT* p0 = C + (long long)(rb + mi * 16) * ldc + cb + ni * 8;
            CT* p1 = p0 + 8ll * ldc;
            if (sizeof(CT) == 2) {
                *(__half2*)p0 = __floats2half2_rn(acc[mi][ni][0] * cs, acc[mi][ni][1] * cs);
                *(__half2*)p1 = __floats2half2_rn(acc[mi][ni][2] * cs, acc[mi][ni][3] * cs);
            } else {
                *(float2*)p0 = make_float2(acc[mi][ni][0] * cs, acc[mi][ni][1] * cs);
                *(float2*)p1 = make_float2(acc[mi][ni][2] * cs, acc[mi][ni][3] * cs);
            }
        }
    }
}

// Batched QKV projection: z selects weight + destination (Q scaled by 1/8)
__global__ __launch_bounds__(256, 2)
void qkv_gemm()
{
    const int z = blockIdx.z;
    __half* C = (z == 0) ? s_Qf : ((z == 1) ? s_Kf : s_Vf);
    gemm_body<__half>(s_Xf, DM, s_WT[z], DM, C, DM, DM, (z == 0) ? 0.125f : 1.0f);
}

// Output projection
__global__ __launch_bounds__(256, 2)
void wo_gemm(float* __restrict__ out)
{
    gemm_body<float>(s_AO, DM, s_WT[3], DM, out, DM, DM, 1.0f);
}

// ---------------------------------------------------------------------------
// Fused differential attention, 512 threads (R13 champion config):
//  warps 0-7 = variant 1, warps 8-15 = variant 2 (each m16 of 128 q rows).
//  64-key K/V tiles, 3-stage prefetch-1 pipeline, ONE __syncthreads per tile.
//  Q fragments hoisted; QK -> exp -> PV interleaved per 16-key slab.
//  exp without max-sub (scores bounded). Combine through smem, GroupNorm
//  + *(0.2) -> fp16 s_AO.  lambda in-block.
// ---------------------------------------------------------------------------
#define BQ     128
#define KT     64
#define QSTR   272                  // 128 halfs + 16B pad
#define SQB2   (BQ * QSTR)          // 34816
#define KTB    (KT * QSTR)          // 17408
#define STG2B  (2 * KTB)            // K + V per stage = 34816
#define NKVST  3
#define FSTR   132                  // combine buffer stride (floats)

__global__ __launch_bounds__(512, 1)
void attn_fused(const float* __restrict__ gnw, const float* __restrict__ gnb,
                const float* __restrict__ lq1, const float* __restrict__ lk1,
                const float* __restrict__ lq2, const float* __restrict__ lk2)
{
    extern __shared__ char sm[];
    const u32 sb  = smem_u32(sm);
    const u32 sQ  = sb;
    const u32 sKV = sb + SQB2;
    float* fbuf = (float*)(sm + SQB2);                 // reuses KV region
    float* shw  = (float*)(sm + SQB2 + NKVST * STG2B);

    const int tid = threadIdx.x;
    const int wid = tid >> 5;
    const int lid = tid & 31;
    const int q0  = blockIdx.x * BQ;
    const int h   = blockIdx.y;
    const int v   = wid >> 3;                          // variant
    const int wm  = (wid & 7) * 16;                    // warp's m-rows

    if (tid < 128) {
        shw[tid]       = gnw[h * 128 + tid];
        shw[128 + tid] = gnb[h * 128 + tid];
    }
    if (wid == 15) {
        float a = lq1[lid] * lk1[lid] + lq1[lid + 32] * lk1[lid + 32];
        float b = lq2[lid] * lk2[lid] + lq2[lid + 32] * lk2[lid + 32];
#pragma unroll
        for (int o = 16; o; o >>= 1) {
            a += __shfl_xor_sync(0xffffffffu, a, o);
            b += __shfl_xor_sync(0xffffffffu, b, o);
        }
        if (lid == 0) shw[256] = __expf(a) - __expf(b) + LAMBDA_INIT;
    }

    // --- Q loader: 512 threads, 4 CP16 each ---
    {
        const int qr = tid >> 2, qs = tid & 3;
        const __half* gq = s_Qf + (long long)(q0 + qr) * DM + h * 128 + qs * 32;
        const u32 d = sQ + (u32)(qr * QSTR + qs * 64);
#pragma unroll
        for (int j = 0; j < 4; j++) CP16(d + j * 16, gq + j * 8);
        CP_COMMIT();
    }
    // --- KV loader mapping: 8 threads/row, 2 CP16 per K and V row ---
    const int kr = tid >> 3, ks = tid & 7;
    const __half* gK0 = s_Kf + (long long)kr * DM + h * 128 + ks * 16;
    const __half* gV0 = s_Vf + (long long)kr * DM + h * 128 + ks * 16;
    const u32 kvDst = (u32)(kr * QSTR + ks * 32);

#define LOADKV(t, st) do {                                                    \
        const u32 d = sKV + (u32)(st) * STG2B + kvDst;                        \
        const __half* gk = gK0 + (long long)(t) * KT * DM;                    \
        const __half* gv = gV0 + (long long)(t) * KT * DM;                    \
        CP16(d, gk);        CP16(d + 16, gk + 8);                             \
        CP16(d + KTB, gv);  CP16(d + KTB + 16, gv + 8);                       \
        CP_COMMIT();                                                          \
    } while (0)

    LOADKV(0, 0);

    // --- fragment lane offsets ---
    const int r8  = lid & 7;
    const int seg = lid >> 3;
    const u32 aOff  = sQ + (u32)((wm + (seg & 1) * 8 + r8) * QSTR + (seg >> 1) * 16 + v * 128);
    const u32 bLane = (u32)(((lid >> 4) * 8 + r8) * QSTR + ((lid >> 3) & 1) * 16 + v * 128);
    const u32 vLane = (u32)((((lid >> 3) & 1) * 8 + r8) * QSTR + (lid >> 4) * 16);

    // --- hoist Q fragments (loop-invariant): wait for Q cp.async group ---
    CP_WAIT1();             // oldest group (Q) retired; KV(0) may be pending
    __syncthreads();
    u32 qf[4][4];
#pragma unroll
    for (int kt = 0; kt < 4; kt++)
        LDSM4(qf[kt], aOff + (u32)(kt * 32));

    float O[16][4];
#pragma unroll
    for (int ni = 0; ni < 16; ni++)
#pragma unroll
        for (int q = 0; q < 4; q++) O[ni][q] = 0.0f;
    float la = 0.0f, lb = 0.0f;

    int stage = 0;
#pragma unroll 1
    for (int t = 0; t < 32; t++) {
        if (t + 1 < 32) {
            // writes stage (t+1)%3 == (t-2)%3: last read at iter t-2,
            // protected by barriers at iterations t-1 and t.
            int nst = stage + 1; if (nst == NKVST) nst = 0;
            LOADKV(t + 1, nst);
            CP_WAIT1();
        } else {
            CP_WAIT0();
        }
        __syncthreads();    // single barrier per tile

        const u32 sK = sKV + (u32)stage * STG2B;
        const u32 sV = sK + KTB;
        stage++; if (stage == NKVST) stage = 0;

        // --- interleaved: per 16-key slab np: QK -> exp -> PV(kt=np) ---
#pragma unroll
        for (int np = 0; np < 4; np++) {
            // S slab = Q * K^T (m16 x n16 x k64)
            float accS[2][4];
#pragma unroll
            for (int q = 0; q < 4; q++) { accS[0][q] = 0.0f; accS[1][q] = 0.0f; }
#pragma unroll
            for (int kt = 0; kt < 4; kt++) {
                u32 b[4];
                LDSM4(b, sK + bLane + (u32)(np * 16 * QSTR + kt * 32));
                MMAH(accS[0], qf[kt], b[0], b[1]);
                MMAH(accS[1], qf[kt], b[2], b[3]);
            }

            // p = exp(s); row-sum; pack as A-fragment for PV step kt=np
            float e0 = __expf(accS[0][0]);
            float e1 = __expf(accS[0][1]);
            float e2 = __expf(accS[0][2]);
            float e3 = __expf(accS[0][3]);
            float f0 = __expf(accS[1][0]);
            float f1 = __expf(accS[1][1]);
            float f2 = __expf(accS[1][2]);
            float f3 = __expf(accS[1][3]);
            la += e0 + e1 + f0 + f1;
            lb += e2 + e3 + f2 + f3;
            u32 a2[4];
            a2[0] = packh2(e0, e1);
            a2[1] = packh2(e2, e3);
            a2[2] = packh2(f0, f1);
            a2[3] = packh2(f2, f3);

            // O += p_slab * V_slab (m16 x n128 x k16)
#pragma unroll
            for (int cp = 0; cp < 8; cp++) {
                u32 d[4];
                LDSM4T(d, sV + vLane + (u32)(np * 16 * QSTR + cp * 32));
                MMAH(O[2 * cp],     a2, d[0], d[1]);
                MMAH(O[2 * cp + 1], a2, d[2], d[3]);
            }
        }
    }
#undef LOADKV

    // --- finish row sums across the quad ---
#pragma unroll
    for (int o = 1; o <= 2; o <<= 1) {
        la += __shfl_xor_sync(0xffffffffu, la, o);
        lb += __shfl_xor_sync(0xffffffffu, lb, o);
    }

    __syncthreads();    // all warps done with KV smem -> fbuf reuse safe

    const int rr = wm + (lid >> 2);
    const int cq = (lid & 3) * 2;

    if (v == 1) {
        const float lam = shw[256];
        const float ia = lam / la, ib = lam / lb;
#pragma unroll
        for (int ni = 0; ni < 16; ni++) {
            *(float2*)&fbuf[rr * FSTR + ni * 8 + cq] =
                make_float2(O[ni][0] * ia, O[ni][1] * ia);
            *(float2*)&fbuf[(rr + 8) * FSTR + ni * 8 + cq] =
                make_float2(O[ni][2] * ib, O[ni][3] * ib);
        }
    } else {
        const float ia = 1.0f / la, ib = 1.0f / lb;
#pragma unroll
        for (int ni = 0; ni < 16; ni++) {
            O[ni][0] *= ia; O[ni][1] *= ia;
            O[ni][2] *= ib; O[ni][3] *= ib;
        }
    }
    __syncthreads();

    if (v == 0) {
        // combine + GroupNorm stats
        float su0 = 0.0f, su1 = 0.0f, sq0 = 0.0f, sq1 = 0.0f;
#pragma unroll
        for (int ni = 0; ni < 16; ni++) {
            float2 f0 = *(const float2*)&fbuf[rr * FSTR + ni * 8 + cq];
            float2 f1 = *(const float2*)&fbuf[(rr + 8) * FSTR + ni * 8 + cq];
            float v0 = O[ni][0] - f0.x;
            float v1 = O[ni][1] - f0.y;
            float v2 = O[ni][2] - f1.x;
            float v3 = O[ni][3] - f1.y;
            O[ni][0] = v0; O[ni][1] = v1; O[ni][2] = v2; O[ni][3] = v3;
            su0 += v0 + v1;  sq0 += v0 * v0 + v1 * v1;
            su1 += v2 + v3;  sq1 += v2 * v2 + v3 * v3;
        }
#pragma unroll
        for (int o = 1; o <= 2; o <<= 1) {
            su0 += __shfl_xor_sync(0xffffffffu, su0, o);
            su1 += __shfl_xor_sync(0xffffffffu, su1, o);
            sq0 += __shfl_xor_sync(0xffffffffu, sq0, o);
            sq1 += __shfl_xor_sync(0xffffffffu, sq1, o);
        }
        const float mn0 = su0 * (1.0f / 128.0f);
        const float mn1 = su1 * (1.0f / 128.0f);
        const float iv0 = rsqrtf(sq0 * (1.0f / 128.0f) - mn0 * mn0 + 1e-5f);
        const float iv1 = rsqrtf(sq1 * (1.0f / 128.0f) - mn1 * mn1 + 1e-5f);

        const int row0 = q0 + rr;
        const float post = 1.0f - LAMBDA_INIT;
#pragma unroll
        for (int ni = 0; ni < 16; ni++) {
            const int c = ni * 8 + cq;
            const float w0 = shw[c],       w1 = shw[c + 1];
            const float b0 = shw[128 + c], b1 = shw[128 + c + 1];
            float v0 = ((O[ni][0] - mn0) * iv0 * w0 + b0) * post;
            float v1 = ((O[ni][1] - mn0) * iv0 * w1 + b1) * post;
            float v2 = ((O[ni][2] - mn1) * iv1 * w0 + b0) * post;
            float v3 = ((O[ni][3] - mn1) * iv1 * w1 + b1) * post;

            const long long off = (long long)row0 * DM + h * 128 + c;
            __half2 hh;
            hh = __floats2half2_rn(v0, v1); *(u32*)(s_AO + off)            = *(u32*)&hh;
            hh = __floats2half2_rn(v2, v3); *(u32*)(s_AO + off + 8ll * DM) = *(u32*)&hh;
        }
    }
}

// ---------------------------------------------------------------------------
// Combined conversion kernel: z<4 -> transpose weight z to fp16;
// z==4 -> elementwise fp32->fp16 of x.  (one launch instead of two)
// ---------------------------------------------------------------------------
__global__ __launch_bounds__(256)
void conv_all_kernel(const float* __restrict__ x,
                     const float* __restrict__ w0, const float* __restrict__ w1,
                     const float* __restrict__ w2, const float* __restrict__ w3)
{
    if (blockIdx.z == 4) {
        // elementwise x conversion: 4096 blocks x 256 threads x 4 elems
        const int i = ((blockIdx.y * 64 + blockIdx.x) * 256 + threadIdx.y * 32 + threadIdx.x) * 4;
        float4 a = *(const float4*)(x + i);
        __half2 h[2];
        h[0] = __floats2half2_rn(a.x, a.y);
        h[1] = __floats2half2_rn(a.z, a.w);
        *(uint2*)(s_Xf + i) = *(uint2*)h;
        return;
    }

    const float* src = (blockIdx.z == 0) ? w0 : (blockIdx.z == 1) ? w1
                     : (blockIdx.z == 2) ? w2 : w3;
    __half* dst = s_WT[blockIdx.z];

    __shared__ float tile[32][33];
    const int bx = blockIdx.x * 32;
    const int by = blockIdx.y * 32;
    const int tx = threadIdx.x, ty = threadIdx.y;
#pragma unroll
    for (int i = 0; i < 32; i += 8)
        tile[ty + i][tx] = src[(long long)(by + ty + i) * DM + bx + tx];
    __syncthreads();
#pragma unroll
    for (int i = 0; i < 32; i += 8)
        dst[(long long)(bx + ty + i) * DM + by + tx] = __float2half_rn(tile[tx][ty + i]);
}

// ---------------------------------------------------------------------------
// Host launch
// ---------------------------------------------------------------------------
extern "C" void kernel_launch(void* const* d_in, const int* in_sizes, int n_in,
                              void* d_out, int out_size)
{
    (void)in_sizes; (void)n_in; (void)out_size;

    const float* x   = (const float*)d_in[0];
    const float* Wq  = (const float*)d_in[1];
    const float* Wk  = (const float*)d_in[2];
    const float* Wv  = (const float*)d_in[3];
    const float* Wo  = (const float*)d_in[4];
    const float* lq1 = (const float*)d_in[5];
    const float* lk1 = (const float*)d_in[6];
    const float* lq2 = (const float*)d_in[7];
    const float* lk2 = (const float*)d_in[8];
    const float* gnw = (const float*)d_in[9];
    const float* gnb = (const float*)d_in[10];
    float* out = (float*)d_out;

    const int SMG = NSTAGE * STAGEB;                     // 81920
    const int SMA = SQB2 + NKVST * STG2B + 1088;         // ~140.4 KB
    cudaFuncSetAttribute(qkv_gemm,   cudaFuncAttributeMaxDynamicSharedMemorySize, SMG);
    cudaFuncSetAttribute(wo_gemm,    cudaFuncAttributeMaxDynamicSharedMemorySize, SMG);
    cudaFuncSetAttribute(attn_fused, cudaFuncAttributeMaxDynamicSharedMemorySize, SMA);

    // input conversions: weights (z=0..3) + x (z=4) in one launch
    conv_all_kernel<<<dim3(64, 64, 5), dim3(32, 8)>>>(x, Wq, Wk, Wv, Wo);

    // QKV projections (one batched launch, z = 0..2)
    qkv_gemm<<<dim3(16, 16, 3), 256, SMG>>>();

    // fused attention + combine + GroupNorm (lambda in-block)
    attn_fused<<<dim3(16, 16), 512, SMA>>>(gnw, gnb, lq1, lk1, lq2, lk2);

    // output projection
    wo_gemm<<<dim3(16, 16), 256, SMG>>>(out);
}

// round 17
// speedup vs baseline: 1.0638x; 1.0044x over previous
#include <cuda_runtime.h>
#include <cuda_fp16.h>

#define SEQ     2048
#define DM      2048
#define NHEAD   16
#define LAMBDA_INIT 0.8f
#define NELEM   (SEQ * DM)

typedef unsigned int u32;

// ---------------- device scratch (no allocations) ----------------
__device__ __half s_Xf[NELEM];                  // x fp16
__device__ __half s_WT[4][NELEM];               // WqT,WkT,WvT,WoT fp16
__device__ __half s_Qf[NELEM];                  // Q fp16, pre-scaled 1/8
__device__ __half s_Kf[NELEM];
__device__ __half s_Vf[NELEM];
__device__ __half s_AO[NELEM];                  // attn out fp16

// ---------------- PTX helpers (sm_80+ portable) ----------------
__device__ __forceinline__ u32 smem_u32(const void* p) {
    u32 a;
    asm("{ .reg .u64 t; cvta.to.shared.u64 t, %1; cvt.u32.u64 %0, t; }" : "=r"(a) : "l"(p));
    return a;
}

#define CP16(saddr, gptr) \
    asm volatile("cp.async.cg.shared.global [%0], [%1], 16;" :: "r"((u32)(saddr)), "l"(gptr))
#define CP_COMMIT() asm volatile("cp.async.commit_group;" ::: "memory")
#define CP_WAIT0()  asm volatile("cp.async.wait_group 0;" ::: "memory")
#define CP_WAIT1()  asm volatile("cp.async.wait_group 1;" ::: "memory")
#define CP_WAIT2()  asm volatile("cp.async.wait_group 2;" ::: "memory")

#define LDSM4(d, addr) \
    asm volatile("ldmatrix.sync.aligned.m8n8.x4.shared.b16 {%0,%1,%2,%3}, [%4];" \
        : "=r"((d)[0]), "=r"((d)[1]), "=r"((d)[2]), "=r"((d)[3]) : "r"((u32)(addr)))
#define LDSM4T(d, addr) \
    asm volatile("ldmatrix.sync.aligned.m8n8.x4.trans.shared.b16 {%0,%1,%2,%3}, [%4];" \
        : "=r"((d)[0]), "=r"((d)[1]), "=r"((d)[2]), "=r"((d)[3]) : "r"((u32)(addr)))

#define MMAH(acc, a, b0, b1) \
    asm volatile("mma.sync.aligned.m16n8k16.row.col.f32.f16.f16.f32 " \
        "{%0,%1,%2,%3}, {%4,%5,%6,%7}, {%8,%9}, {%0,%1,%2,%3};" \
        : "+f"((acc)[0]), "+f"((acc)[1]), "+f"((acc)[2]), "+f"((acc)[3]) \
        : "r"((a)[0]), "r"((a)[1]), "r"((a)[2]), "r"((a)[3]), "r"(b0), "r"(b1))

__device__ __forceinline__ u32 packh2(float a, float b) {
    __half2 t = __floats2half2_rn(a, b);
    return *(u32*)&t;
}

// ---------------------------------------------------------------------------
// Dense fp16 HMMA GEMM body (m64n32 warp tiles, 256 threads).
// K-chunk 32, 4 smem buffers, cp.async prefetch distance 2, ONE
// __syncthreads per chunk.  B operand via 2x LDSM4 per k16 step (was 4x
// LDSM2) — identical bytes/registers, half the shared-pipe issues.
// C[m][n] = cs * sum_k A[m][k]*B[n][k].  Tile 128x128.
// ---------------------------------------------------------------------------
#define TSTRIDE 80
#define TILEB   (128 * TSTRIDE)
#define STAGEB  (2 * TILEB)          // A tile + B tile = 20480 B
#define OFF_B   TILEB
#define NSTAGE  4

template<typename CT>
__device__ __forceinline__ void gemm_body(
    const __half* __restrict__ A, int lda,
    const __half* __restrict__ B, int ldb,
    CT* __restrict__ C, int ldc, int K, float cs)
{
    extern __shared__ char smem[];
    const u32 sb = smem_u32(smem);

    const int tid = threadIdx.x;
    const int wid = tid >> 5;
    const int lid = tid & 31;
    const int row0 = blockIdx.y * 128;
    const int col0 = blockIdx.x * 128;
    const int wm0 = (wid & 1) * 64;
    const int wn0 = (wid >> 1) * 32;

    const int lr = tid >> 1;
    const int lq = tid & 1;
    const __half* gA = A + (long long)(row0 + lr) * lda + lq * 16;
    const __half* gB = B + (long long)(col0 + lr) * ldb + lq * 16;
    const u32 sRow = sb + (u32)(lr * TSTRIDE + lq * 32);

    const int r8  = lid & 7;
    const int seg = lid >> 3;
    // A x4: mat0 (m0-7,k0-7), mat1 (m8-15,k0-7), mat2 (m0-7,k8-15), mat3 (m8-15,k8-15)
    const u32 aLane = (u32)(((seg & 1) * 8 + r8) * TSTRIDE + (seg >> 1) * 16);
    // B x4: mat0 (n0-7,k0-7), mat1 (n0-7,k8-15), mat2 (n8-15,k0-7), mat3 (n8-15,k8-15)
    const u32 bLane = (u32)(((seg >> 1) * 8 + r8) * TSTRIDE + (seg & 1) * 16);

    float acc[4][4][4];
#pragma unroll
    for (int mi = 0; mi < 4; mi++)
#pragma unroll
        for (int ni = 0; ni < 4; ni++)
#pragma unroll
            for (int q = 0; q < 4; q++) acc[mi][ni][q] = 0.0f;

    const int nch = K >> 5;

#define LOADC(ck, st) do {                                                    \
        const u32 s0 = sRow + (u32)(st) * STAGEB;                             \
        const long long kg = (long long)(ck) * 32;                            \
        CP16(s0, gA + kg);          CP16(s0 + 16, gA + kg + 8);               \
        CP16(s0 + OFF_B, gB + kg);  CP16(s0 + OFF_B + 16, gB + kg + 8);       \
        CP_COMMIT();                                                          \
    } while (0)

    // prologue: 2 chunks in flight (prefetch distance 2, 4 buffers)
    LOADC(0, 0);
    LOADC(1, 1);

    for (int ck = 0; ck < nch; ck++) {
        if (ck + 2 < nch) {
            // writes stage (ck+2)&3 == (ck-2)&3: last read at iter ck-2,
            // protected by the barriers at iterations ck-1 and ck.
            LOADC(ck + 2, (ck + 2) & (NSTAGE - 1));
            CP_WAIT2();
        } else if (ck + 1 < nch) {
            CP_WAIT1();
        } else {
            CP_WAIT0();
        }
        __syncthreads();    // single barrier per chunk: visibility + stage guard

        const u32 stg   = sb + (u32)((ck & (NSTAGE - 1)) * STAGEB);
        const u32 aBase = stg + (u32)(wm0 * TSTRIDE) + aLane;
        const u32 bBase = stg + (u32)(OFF_B + wn0 * TSTRIDE) + bLane;

#pragma unroll
        for (int ks = 0; ks < 2; ks++) {
            const u32 kb = (u32)(ks * 32);
            u32 bb[2][4];
#pragma unroll
            for (int j = 0; j < 2; j++)
                LDSM4(bb[j], bBase + kb + (u32)(j * 16 * TSTRIDE));
            u32 a[4][4];
#pragma unroll
            for (int mi = 0; mi < 4; mi++)
                LDSM4(a[mi], aBase + kb + (u32)(mi * 16 * TSTRIDE));
#pragma unroll
            for (int ni = 0; ni < 4; ni++) {
                const u32 b0 = bb[ni >> 1][(ni & 1) * 2];
                const u32 b1 = bb[ni >> 1][(ni & 1) * 2 + 1];
#pragma unroll
                for (int mi = 0; mi < 4; mi++)
                    MMAH(acc[mi][ni], a[mi], b0, b1);
            }
        }
    }
#undef LOADC

    const int rb = row0 + wm0 + (lid >> 2);
    const int cb = col0 + wn0 + (lid & 3) * 2;
#pragma unroll
    for (int mi = 0; mi < 4; mi++) {
#pragma unroll
        for (int ni = 0; ni < 4; ni++) {
            CT* p0 = C + (long long)(rb + mi * 16) * ldc + cb + ni * 8;
            CT* p1 = p0 + 8ll * ldc;
            if (sizeof(CT) == 2) {
                *(__half2*)p0 = __floats2half2_rn(acc[mi][ni][0] * cs, acc[mi][ni][1] * cs);
                *(__half2*)p1 = __floats2half2_rn(acc[mi][ni][2] * cs, acc[mi][ni][3] * cs);
            } else {
                *(float2*)p0 = make_float2(acc[mi][ni][0] * cs, acc[mi][ni][1] * cs);
                *(float2*)p1 = make_float2(acc[mi][ni][2] * cs, acc[mi][ni][3] * cs);
            }
        }
    }
}

// Batched QKV projection: z selects weight + destination (Q scaled by 1/8)
__global__ __launch_bounds__(256, 2)
void qkv_gemm()
{
    const int z = blockIdx.z;
    __half* C = (z == 0) ? s_Qf : ((z == 1) ? s_Kf : s_Vf);
    gemm_body<__half>(s_Xf, DM, s_WT[z], DM, C, DM, DM, (z == 0) ? 0.125f : 1.0f);
}

// Output projection
__global__ __launch_bounds__(256, 2)
void wo_gemm(float* __restrict__ out)
{
    gemm_body<float>(s_AO, DM, s_WT[3], DM, out, DM, DM, 1.0f);
}

// ---------------------------------------------------------------------------
// Fused differential attention, 512 threads (champion config):
//  warps 0-7 = variant 1, warps 8-15 = variant 2 (each m16 of 128 q rows).
//  64-key K/V tiles, 3-stage prefetch-1 pipeline, ONE __syncthreads per tile.
//  Q fragments hoisted; QK -> exp -> PV interleaved per 16-key slab.
//  exp without max-sub (scores bounded). Combine through smem, GroupNorm
//  + *(0.2) -> fp16 s_AO.  lambda in-block.
// ---------------------------------------------------------------------------
#define BQ     128
#define KT     64
#define QSTR   272                  // 128 halfs + 16B pad
#define SQB2   (BQ * QSTR)          // 34816
#define KTB    (KT * QSTR)          // 17408
#define STG2B  (2 * KTB)            // K + V per stage = 34816
#define NKVST  3
#define FSTR   132                  // combine buffer stride (floats)

__global__ __launch_bounds__(512, 1)
void attn_fused(const float* __restrict__ gnw, const float* __restrict__ gnb,
                const float* __restrict__ lq1, const float* __restrict__ lk1,
                const float* __restrict__ lq2, const float* __restrict__ lk2)
{
    extern __shared__ char sm[];
    const u32 sb  = smem_u32(sm);
    const u32 sQ  = sb;
    const u32 sKV = sb + SQB2;
    float* fbuf = (float*)(sm + SQB2);                 // reuses KV region
    float* shw  = (float*)(sm + SQB2 + NKVST * STG2B);

    const int tid = threadIdx.x;
    const int wid = tid >> 5;
    const int lid = tid & 31;
    const int q0  = blockIdx.x * BQ;
    const int h   = blockIdx.y;
    const int v   = wid >> 3;                          // variant
    const int wm  = (wid & 7) * 16;                    // warp's m-rows

    if (tid < 128) {
        shw[tid]       = gnw[h * 128 + tid];
        shw[128 + tid] = gnb[h * 128 + tid];
    }
    if (wid == 15) {
        float a = lq1[lid] * lk1[lid] + lq1[lid + 32] * lk1[lid + 32];
        float b = lq2[lid] * lk2[lid] + lq2[lid + 32] * lk2[lid + 32];
#pragma unroll
        for (int o = 16; o; o >>= 1) {
            a += __shfl_xor_sync(0xffffffffu, a, o);
            b += __shfl_xor_sync(0xffffffffu, b, o);
        }
        if (lid == 0) shw[256] = __expf(a) - __expf(b) + LAMBDA_INIT;
    }

    // --- Q loader: 512 threads, 4 CP16 each ---
    {
        const int qr = tid >> 2, qs = tid & 3;
        const __half* gq = s_Qf + (long long)(q0 + qr) * DM + h * 128 + qs * 32;
        const u32 d = sQ + (u32)(qr * QSTR + qs * 64);
#pragma unroll
        for (int j = 0; j < 4; j++) CP16(d + j * 16, gq + j * 8);
        CP_COMMIT();
    }
    // --- KV loader mapping: 8 threads/row, 2 CP16 per K and V row ---
    const int kr = tid >> 3, ks = tid & 7;
    const __half* gK0 = s_Kf + (long long)kr * DM + h * 128 + ks * 16;
    const __half* gV0 = s_Vf + (long long)kr * DM + h * 128 + ks * 16;
    const u32 kvDst = (u32)(kr * QSTR + ks * 32);

#define LOADKV(t, st) do {                                                    \
        const u32 d = sKV + (u32)(st) * STG2B + kvDst;                        \
        const __half* gk = gK0 + (long long)(t) * KT * DM;                    \
        const __half* gv = gV0 + (long long)(t) * KT * DM;                    \
        CP16(d, gk);        CP16(d + 16, gk + 8);                             \
        CP16(d + KTB, gv);  CP16(d + KTB + 16, gv + 8);                       \
        CP_COMMIT();                                                          \
    } while (0)

    LOADKV(0, 0);

    // --- fragment lane offsets ---
    const int r8  = lid & 7;
    const int seg = lid >> 3;
    const u32 aOff  = sQ + (u32)((wm + (seg & 1) * 8 + r8) * QSTR + (seg >> 1) * 16 + v * 128);
    const u32 bLane = (u32)(((lid >> 4) * 8 + r8) * QSTR + ((lid >> 3) & 1) * 16 + v * 128);
    const u32 vLane = (u32)((((lid >> 3) & 1) * 8 + r8) * QSTR + (lid >> 4) * 16);

    // --- hoist Q fragments (loop-invariant): wait for Q cp.async group ---
    CP_WAIT1();             // oldest group (Q) retired; KV(0) may be pending
    __syncthreads();
    u32 qf[4][4];
#pragma unroll
    for (int kt = 0; kt < 4; kt++)
        LDSM4(qf[kt], aOff + (u32)(kt * 32));

    float O[16][4];
#pragma unroll
    for (int ni = 0; ni < 16; ni++)
#pragma unroll
        for (int q = 0; q < 4; q++) O[ni][q] = 0.0f;
    float la = 0.0f, lb = 0.0f;

    int stage = 0;
#pragma unroll 1
    for (int t = 0; t < 32; t++) {
        if (t + 1 < 32) {
            // writes stage (t+1)%3 == (t-2)%3: last read at iter t-2,
            // protected by barriers at iterations t-1 and t.
            int nst = stage + 1; if (nst == NKVST) nst = 0;
            LOADKV(t + 1, nst);
            CP_WAIT1();
        } else {
            CP_WAIT0();
        }
        __syncthreads();    // single barrier per tile

        const u32 sK = sKV + (u32)stage * STG2B;
        const u32 sV = sK + KTB;
        stage++; if (stage == NKVST) stage = 0;

        // --- interleaved: per 16-key slab np: QK -> exp -> PV(kt=np) ---
#pragma unroll
        for (int np = 0; np < 4; np++) {
            // S slab = Q * K^T (m16 x n16 x k64)
            float accS[2][4];
#pragma unroll
            for (int q = 0; q < 4; q++) { accS[0][q] = 0.0f; accS[1][q] = 0.0f; }
#pragma unroll
            for (int kt = 0; kt < 4; kt++) {
                u32 b[4];
                LDSM4(b, sK + bLane + (u32)(np * 16 * QSTR + kt * 32));
                MMAH(accS[0], qf[kt], b[0], b[1]);
                MMAH(accS[1], qf[kt], b[2], b[3]);
            }

            // p = exp(s); row-sum; pack as A-fragment for PV step kt=np
            float e0 = __expf(accS[0][0]);
            float e1 = __expf(accS[0][1]);
            float e2 = __expf(accS[0][2]);
            float e3 = __expf(accS[0][3]);
            float f0 = __expf(accS[1][0]);
            float f1 = __expf(accS[1][1]);
            float f2 = __expf(accS[1][2]);
            float f3 = __expf(accS[1][3]);
            la += e0 + e1 + f0 + f1;
            lb += e2 + e3 + f2 + f3;
            u32 a2[4];
            a2[0] = packh2(e0, e1);
            a2[1] = packh2(e2, e3);
            a2[2] = packh2(f0, f1);
            a2[3] = packh2(f2, f3);

            // O += p_slab * V_slab (m16 x n128 x k16)
#pragma unroll
            for (int cp = 0; cp < 8; cp++) {
                u32 d[4];
                LDSM4T(d, sV + vLane + (u32)(np * 16 * QSTR + cp * 32));
                MMAH(O[2 * cp],     a2, d[0], d[1]);
                MMAH(O[2 * cp + 1], a2, d[2], d[3]);
            }
        }
    }
#undef LOADKV

    // --- finish row sums across the quad ---
#pragma unroll
    for (int o = 1; o <= 2; o <<= 1) {
        la += __shfl_xor_sync(0xffffffffu, la, o);
        lb += __shfl_xor_sync(0xffffffffu, lb, o);
    }

    __syncthreads();    // all warps done with KV smem -> fbuf reuse safe

    const int rr = wm + (lid >> 2);
    const int cq = (lid & 3) * 2;

    if (v == 1) {
        const float lam = shw[256];
        const float ia = lam / la, ib = lam / lb;
#pragma unroll
        for (int ni = 0; ni < 16; ni++) {
            *(float2*)&fbuf[rr * FSTR + ni * 8 + cq] =
                make_float2(O[ni][0] * ia, O[ni][1] * ia);
            *(float2*)&fbuf[(rr + 8) * FSTR + ni * 8 + cq] =
                make_float2(O[ni][2] * ib, O[ni][3] * ib);
        }
    } else {
        const float ia = 1.0f / la, ib = 1.0f / lb;
#pragma unroll
        for (int ni = 0; ni < 16; ni++) {
            O[ni][0] *= ia; O[ni][1] *= ia;
            O[ni][2] *= ib; O[ni][3] *= ib;
        }
    }
    __syncthreads();

    if (v == 0) {
        // combine + GroupNorm stats
        float su0 = 0.0f, su1 = 0.0f, sq0 = 0.0f, sq1 = 0.0f;
#pragma unroll
        for (int ni = 0; ni < 16; ni++) {
            float2 f0 = *(const float2*)&fbuf[rr * FSTR + ni * 8 + cq];
            float2 f1 = *(const float2*)&fbuf[(rr + 8) * FSTR + ni * 8 + cq];
            float v0 = O[ni][0] - f0.x;
            float v1 = O[ni][1] - f0.y;
            float v2 = O[ni][2] - f1.x;
            float v3 = O[ni][3] - f1.y;
            O[ni][0] = v0; O[ni][1] = v1; O[ni][2] = v2; O[ni][3] = v3;
            su0 += v0 + v1;  sq0 += v0 * v0 + v1 * v1;
            su1 += v2 + v3;  sq1 += v2 * v2 + v3 * v3;
        }
#pragma unroll
        for (int o = 1; o <= 2; o <<= 1) {
            su0 += __shfl_xor_sync(0xffffffffu, su0, o);
            su1 += __shfl_xor_sync(0xffffffffu, su1, o);
            sq0 += __shfl_xor_sync(0xffffffffu, sq0, o);
            sq1 += __shfl_xor_sync(0xffffffffu, sq1, o);
        }
        const float mn0 = su0 * (1.0f / 128.0f);
        const float mn1 = su1 * (1.0f / 128.0f);
        const float iv0 = rsqrtf(sq0 * (1.0f / 128.0f) - mn0 * mn0 + 1e-5f);
        const float iv1 = rsqrtf(sq1 * (1.0f / 128.0f) - mn1 * mn1 + 1e-5f);

        const int row0 = q0 + rr;
        const float post = 1.0f - LAMBDA_INIT;
#pragma unroll
        for (int ni = 0; ni < 16; ni++) {
            const int c = ni * 8 + cq;
            const float w0 = shw[c],       w1 = shw[c + 1];
            const float b0 = shw[128 + c], b1 = shw[128 + c + 1];
            float v0 = ((O[ni][0] - mn0) * iv0 * w0 + b0) * post;
            float v1 = ((O[ni][1] - mn0) * iv0 * w1 + b1) * post;
            float v2 = ((O[ni][2] - mn1) * iv1 * w0 + b0) * post;
            float v3 = ((O[ni][3] - mn1) * iv1 * w1 + b1) * post;

            const long long off = (long long)row0 * DM + h * 128 + c;
            __half2 hh;
            hh = __floats2half2_rn(v0, v1); *(u32*)(s_AO + off)            = *(u32*)&hh;
            hh = __floats2half2_rn(v2, v3); *(u32*)(s_AO + off + 8ll * DM) = *(u32*)&hh;
        }
    }
}

// ---------------------------------------------------------------------------
// Combined conversion kernel: z<4 -> transpose weight z to fp16;
// z==4 -> elementwise fp32->fp16 of x.  (one launch)
// ---------------------------------------------------------------------------
__global__ __launch_bounds__(256)
void conv_all_kernel(const float* __restrict__ x,
                     const float* __restrict__ w0, const float* __restrict__ w1,
                     const float* __restrict__ w2, const float* __restrict__ w3)
{
    if (blockIdx.z == 4) {
        const int i = ((blockIdx.y * 64 + blockIdx.x) * 256 + threadIdx.y * 32 + threadIdx.x) * 4;
        float4 a = *(const float4*)(x + i);
        __half2 h[2];
        h[0] = __floats2half2_rn(a.x, a.y);
        h[1] = __floats2half2_rn(a.z, a.w);
        *(uint2*)(s_Xf + i) = *(uint2*)h;
        return;
    }

    const float* src = (blockIdx.z == 0) ? w0 : (blockIdx.z == 1) ? w1
                     : (blockIdx.z == 2) ? w2 : w3;
    __half* dst = s_WT[blockIdx.z];

    __shared__ float tile[32][33];
    const int bx = blockIdx.x * 32;
    const int by = blockIdx.y * 32;
    const int tx = threadIdx.x, ty = threadIdx.y;
#pragma unroll
    for (int i = 0; i < 32; i += 8)
        tile[ty + i][tx] = src[(long long)(by + ty + i) * DM + bx + tx];
    __syncthreads();
#pragma unroll
    for (int i = 0; i < 32; i += 8)
        dst[(long long)(bx + ty + i) * DM + by + tx] = __float2half_rn(tile[tx][ty + i]);
}

// ---------------------------------------------------------------------------
// Host launch
// ---------------------------------------------------------------------------
extern "C" void kernel_launch(void* const* d_in, const int* in_sizes, int n_in,
                              void* d_out, int out_size)
{
    (void)in_sizes; (void)n_in; (void)out_size;

    const float* x   = (const float*)d_in[0];
    const float* Wq  = (const float*)d_in[1];
    const float* Wk  = (const float*)d_in[2];
    const float* Wv  = (const float*)d_in[3];
    const float* Wo  = (const float*)d_in[4];
    const float* lq1 = (const float*)d_in[5];
    const float* lk1 = (const float*)d_in[6];
    const float* lq2 = (const float*)d_in[7];
    const float* lk2 = (const float*)d_in[8];
    const float* gnw = (const float*)d_in[9];
    const float* gnb = (const float*)d_in[10];
    float* out = (float*)d_out;

    const int SMG = NSTAGE * STAGEB;                     // 81920
    const int SMA = SQB2 + NKVST * STG2B + 1088;         // ~140.4 KB
    cudaFuncSetAttribute(qkv_gemm,   cudaFuncAttributeMaxDynamicSharedMemorySize, SMG);
    cudaFuncSetAttribute(wo_gemm,    cudaFuncAttributeMaxDynamicSharedMemorySize, SMG);
    cudaFuncSetAttribute(attn_fused, cudaFuncAttributeMaxDynamicSharedMemorySize, SMA);

    // input conversions: weights (z=0..3) + x (z=4) in one launch
    conv_all_kernel<<<dim3(64, 64, 5), dim3(32, 8)>>>(x, Wq, Wk, Wv, Wo);

    // QKV projections (one batched launch, z = 0..2)
    qkv_gemm<<<dim3(16, 16, 3), 256, SMG>>>();

    // fused attention + combine + GroupNorm (lambda in-block)
    attn_fused<<<dim3(16, 16), 512, SMA>>>(gnw, gnb, lq1, lk1, lq2, lk2);

    // output projection
    wo_gemm<<<dim3(16, 16), 256, SMG>>>(out);
}